// round 3
// baseline (speedup 1.0000x reference)
#include <cuda_runtime.h>
#include <cuda_fp16.h>

#define BATCH 16
#define NMAT  1024
#define DDIM  256
#define ITERS 101          // 100 scan steps + 1 final sinkhorn_step
#define NBLK_PER_B 9
#define GRID_SINK (BATCH * NBLK_PER_B)   // 144 blocks, all resident on 148 SMs
#define TPB_SINK  512                    // 16 warps

typedef unsigned long long ull;

// ---------------- f32x2 helpers (FFMA2 — only reachable via PTX) ----------------
__device__ __forceinline__ void ffma2(ull& d, ull a, ull b) {
    asm("fma.rn.f32x2 %0, %1, %2, %3;" : "=l"(d) : "l"(a), "l"(b), "l"(d));
}
__device__ __forceinline__ ull packf2(float lo, float hi) {
    ull r; asm("mov.b64 %0, {%1, %2};" : "=l"(r) : "f"(lo), "f"(hi)); return r;
}
__device__ __forceinline__ float2 unpackf2(ull v) {
    float lo, hi; asm("mov.b64 {%0, %1}, %2;" : "=f"(lo), "=f"(hi) : "l"(v));
    return make_float2(lo, hi);
}

// ---------------- device scratch (no allocations allowed) ----------------
__device__ float  g_nA[BATCH * NMAT * DDIM];                 // 16.8 MB
__device__ float  g_nB[BATCH * NMAT * DDIM];                 // 16.8 MB
__device__ __half g_K[(size_t)BATCH * NMAT * NMAT];          // 33.5 MB (L2-resident)
__device__ float  g_part[2][BATCH][NBLK_PER_B][NMAT];        // double-buffered col partials
__device__ unsigned g_bar_count;
__device__ unsigned g_bar_gen;

// ---------------- l2 normalize: warp per row (256 elems) ----------------
__global__ void norm_kernel(const float* __restrict__ in, int which) {
    int w = threadIdx.x >> 5, lane = threadIdx.x & 31;
    int row = blockIdx.x * 8 + w;                      // 2048 blocks * 8 = 16384 rows
    const float4* src = reinterpret_cast<const float4*>(in) + (size_t)row * 64;
    float4 x0 = src[lane];
    float4 x1 = src[lane + 32];
    float s = x0.x * x0.x + x0.y * x0.y + x0.z * x0.z + x0.w * x0.w
            + x1.x * x1.x + x1.y * x1.y + x1.z * x1.z + x1.w * x1.w;
    #pragma unroll
    for (int off = 16; off; off >>= 1) s += __shfl_xor_sync(0xffffffffu, s, off);
    float r = rsqrtf(fmaxf(s, 1e-12f));
    float* dst = (which ? g_nB : g_nA) + (size_t)row * 256;
    reinterpret_cast<float4*>(dst)[lane]      = make_float4(x0.x*r, x0.y*r, x0.z*r, x0.w*r);
    reinterpret_cast<float4*>(dst)[lane + 32] = make_float4(x1.x*r, x1.y*r, x1.z*r, x1.w*r);
}

// ---------------- GEMM: S = nA * nB^T per batch, K = fp16(exp(5*clamp(S))) ----------------
// grid (8, 8, 16), block 256, 128x128 tile, 8x8 per thread, BK=32, FFMA2 inner loop.
// A stored DUPLICATED in smem so LDS returns (a,a) pairs; B pairs are naturally adjacent.
__global__ void __launch_bounds__(256) gemm_expk_kernel(float* __restrict__ Sout) {
    __shared__ float As2[32 * 256];  // [k][2*i + {0,1}] both = A[i][k]
    __shared__ float Bs [32 * 128];  // [k][j]
    const int b  = blockIdx.z;
    const int i0 = blockIdx.y * 128;
    const int j0 = blockIdx.x * 128;
    const float* Ag = g_nA + (size_t)b * NMAT * DDIM;
    const float* Bg = g_nB + (size_t)b * NMAT * DDIM;
    const int tid = threadIdx.x;
    const int tx = tid & 15, ty = tid >> 4;
    const int lr = tid >> 3;     // 0..31 row within chunk
    const int lc = tid & 7;      // float4 group within 32 k-cols

    ull acc2[8][4];
    #pragma unroll
    for (int i = 0; i < 8; i++)
        #pragma unroll
        for (int j = 0; j < 4; j++) acc2[i][j] = 0ull;

    for (int kc = 0; kc < 8; kc++) {
        __syncthreads();
        #pragma unroll
        for (int g = 0; g < 4; g++) {
            int row = lr + 32 * g;
            float4 av = *reinterpret_cast<const float4*>(
                &Ag[(size_t)(i0 + row) * DDIM + kc * 32 + lc * 4]);
            As2[(lc*4+0)*256 + 2*row] = av.x;  As2[(lc*4+0)*256 + 2*row + 1] = av.x;
            As2[(lc*4+1)*256 + 2*row] = av.y;  As2[(lc*4+1)*256 + 2*row + 1] = av.y;
            As2[(lc*4+2)*256 + 2*row] = av.z;  As2[(lc*4+2)*256 + 2*row + 1] = av.z;
            As2[(lc*4+3)*256 + 2*row] = av.w;  As2[(lc*4+3)*256 + 2*row + 1] = av.w;
            float4 bv = *reinterpret_cast<const float4*>(
                &Bg[(size_t)(j0 + row) * DDIM + kc * 32 + lc * 4]);
            Bs[(lc*4+0)*128 + row] = bv.x;
            Bs[(lc*4+1)*128 + row] = bv.y;
            Bs[(lc*4+2)*128 + row] = bv.z;
            Bs[(lc*4+3)*128 + row] = bv.w;
        }
        __syncthreads();
        #pragma unroll
        for (int k = 0; k < 32; k++) {
            // 8 duplicated a-pairs: (a_ii, a_ii), 16B-aligned
            const ulonglong2* ap2 = reinterpret_cast<const ulonglong2*>(&As2[k*256 + ty*16]);
            ulonglong2 A0 = ap2[0], A1 = ap2[1], A2 = ap2[2], A3 = ap2[3];
            ull ap[8] = {A0.x, A0.y, A1.x, A1.y, A2.x, A2.y, A3.x, A3.y};
            ull bp[4];
            #pragma unroll
            for (int j = 0; j < 4; j++)
                bp[j] = *reinterpret_cast<const ull*>(&Bs[k*128 + tx*8 + 2*j]);
            #pragma unroll
            for (int ii = 0; ii < 8; ii++)
                #pragma unroll
                for (int j = 0; j < 4; j++)
                    ffma2(acc2[ii][j], ap[ii], bp[j]);
        }
    }

    #pragma unroll
    for (int ii = 0; ii < 8; ii++) {
        int i = i0 + ty * 8 + ii;
        size_t base = ((size_t)b << 20) + (size_t)i * NMAT + j0 + tx * 8;
        float2 p0 = unpackf2(acc2[ii][0]);
        float2 p1 = unpackf2(acc2[ii][1]);
        float2 p2 = unpackf2(acc2[ii][2]);
        float2 p3 = unpackf2(acc2[ii][3]);
        *reinterpret_cast<float4*>(&Sout[base])     = make_float4(p0.x, p0.y, p1.x, p1.y);
        *reinterpret_cast<float4*>(&Sout[base + 4]) = make_float4(p2.x, p2.y, p3.x, p3.y);
        float e0 = __expf(5.f * fminf(fmaxf(p0.x, -3.f), 3.f));
        float e1 = __expf(5.f * fminf(fmaxf(p0.y, -3.f), 3.f));
        float e2 = __expf(5.f * fminf(fmaxf(p1.x, -3.f), 3.f));
        float e3 = __expf(5.f * fminf(fmaxf(p1.y, -3.f), 3.f));
        float e4 = __expf(5.f * fminf(fmaxf(p2.x, -3.f), 3.f));
        float e5 = __expf(5.f * fminf(fmaxf(p2.y, -3.f), 3.f));
        float e6 = __expf(5.f * fminf(fmaxf(p3.x, -3.f), 3.f));
        float e7 = __expf(5.f * fminf(fmaxf(p3.y, -3.f), 3.f));
        __half2 h0 = __floats2half2_rn(e0, e1);
        __half2 h1 = __floats2half2_rn(e2, e3);
        __half2 h2 = __floats2half2_rn(e4, e5);
        __half2 h3 = __floats2half2_rn(e6, e7);
        uint4 kq;
        kq.x = *reinterpret_cast<unsigned*>(&h0);
        kq.y = *reinterpret_cast<unsigned*>(&h1);
        kq.z = *reinterpret_cast<unsigned*>(&h2);
        kq.w = *reinterpret_cast<unsigned*>(&h3);
        *reinterpret_cast<uint4*>(&g_K[base]) = kq;
    }
}

// ---------------- grid barrier (all 144 blocks resident by construction) ----------------
__device__ __forceinline__ void grid_barrier() {
    __syncthreads();
    if (threadIdx.x == 0) {
        __threadfence();
        unsigned gen = *reinterpret_cast<volatile unsigned*>(&g_bar_gen);
        if (atomicAdd(&g_bar_count, 1u) == GRID_SINK - 1) {
            g_bar_count = 0;
            __threadfence();
            atomicAdd(&g_bar_gen, 1u);
        } else {
            while (*reinterpret_cast<volatile unsigned*>(&g_bar_gen) == gen) {
                __nanosleep(32);
            }
        }
        __threadfence();
    }
    __syncthreads();
}

// ---------------- persistent Sinkhorn: 101 fused (row+col) passes over fp16 K ----------------
// Block = (batch b, slice r of 9). Warp processes whole rows; lane owns cols {256k + 8*lane + m}.
__global__ void __launch_bounds__(TPB_SINK, 1) sinkhorn_kernel(float* __restrict__ Pout) {
    const int b = blockIdx.x / NBLK_PER_B;
    const int r = blockIdx.x % NBLK_PER_B;
    const int row0  = r * 114;
    const int nrows = (r == 8) ? 112 : 114;          // 8*114 + 112 = 1024
    const int tid = threadIdx.x, w = tid >> 5, lane = tid & 31;

    extern __shared__ float sm[];
    float* v_s     = sm;            // 1024
    float* u_s     = sm + 1024;     // 128 (114 used)
    float* colpart = sm + 1152;     // 16 * 1024

    const __half* Kb = g_K + ((size_t)b << 20);

    ull vp[16];   // packed v pairs for owned columns
    ull ca[16];   // packed column accumulators

    for (int t = 0; t < ITERS; t++) {
        const int wb = t & 1;        // buffer written this iteration
        // ---- phase A: build v ----
        if (t == 0) {
            #pragma unroll
            for (int m = 0; m < 16; m++) vp[m] = packf2(1.0f, 1.0f);
        } else {
            const int rb = wb ^ 1;   // buffer written by iteration t-1
            for (int c = tid; c < NMAT; c += TPB_SINK) {
                float s = 0.f;
                #pragma unroll
                for (int rr = 0; rr < NBLK_PER_B; rr++) s += g_part[rb][b][rr][c];
                v_s[c] = 1.0f / s;
            }
            __syncthreads();
            #pragma unroll
            for (int k = 0; k < 4; k++) {
                float4 va = *reinterpret_cast<const float4*>(&v_s[256*k + 8*lane]);
                float4 vb = *reinterpret_cast<const float4*>(&v_s[256*k + 8*lane + 4]);
                vp[4*k+0] = packf2(va.x, va.y);
                vp[4*k+1] = packf2(va.z, va.w);
                vp[4*k+2] = packf2(vb.x, vb.y);
                vp[4*k+3] = packf2(vb.z, vb.w);
            }
        }
        #pragma unroll
        for (int m = 0; m < 16; m++) ca[m] = 0ull;

        // ---- phase B: fused row matvec + col accumulate (one K pass) ----
        for (int il = w; il < nrows; il += 16) {
            const int i = row0 + il;
            const uint4* Krow = reinterpret_cast<const uint4*>(Kb + (size_t)i * NMAT);
            ull kf[16];
            ull d0 = 0ull, d1 = 0ull;
            #pragma unroll
            for (int k = 0; k < 4; k++) {
                uint4 q = Krow[32*k + lane];
                float2 f0 = __half22float2(*reinterpret_cast<__half2*>(&q.x));
                float2 f1 = __half22float2(*reinterpret_cast<__half2*>(&q.y));
                float2 f2 = __half22float2(*reinterpret_cast<__half2*>(&q.z));
                float2 f3 = __half22float2(*reinterpret_cast<__half2*>(&q.w));
                kf[4*k+0] = packf2(f0.x, f0.y);
                kf[4*k+1] = packf2(f1.x, f1.y);
                kf[4*k+2] = packf2(f2.x, f2.y);
                kf[4*k+3] = packf2(f3.x, f3.y);
                ffma2(d0, kf[4*k+0], vp[4*k+0]);
                ffma2(d1, kf[4*k+1], vp[4*k+1]);
                ffma2(d0, kf[4*k+2], vp[4*k+2]);
                ffma2(d1, kf[4*k+3], vp[4*k+3]);
            }
            float2 dd0 = unpackf2(d0), dd1 = unpackf2(d1);
            float dot = (dd0.x + dd0.y) + (dd1.x + dd1.y);
            #pragma unroll
            for (int off = 16; off; off >>= 1) dot += __shfl_xor_sync(0xffffffffu, dot, off);
            float u = 1.0f / dot;
            if (lane == 0) u_s[il] = u;
            ull up = packf2(u, u);
            #pragma unroll
            for (int m = 0; m < 16; m++) ffma2(ca[m], up, kf[m]);
        }

        // ---- phase C: per-warp partials -> block partial -> global ----
        #pragma unroll
        for (int k = 0; k < 4; k++) {
            float2 p0 = unpackf2(ca[4*k+0]);
            float2 p1 = unpackf2(ca[4*k+1]);
            float2 p2 = unpackf2(ca[4*k+2]);
            float2 p3 = unpackf2(ca[4*k+3]);
            *reinterpret_cast<float4*>(&colpart[w*1024 + 256*k + 8*lane]) =
                make_float4(p0.x, p0.y, p1.x, p1.y);
            *reinterpret_cast<float4*>(&colpart[w*1024 + 256*k + 8*lane + 4]) =
                make_float4(p2.x, p2.y, p3.x, p3.y);
        }
        __syncthreads();
        for (int c = tid; c < NMAT; c += TPB_SINK) {
            float s = 0.f;
            #pragma unroll
            for (int ww = 0; ww < 16; ww++) s += colpart[ww * 1024 + c];
            g_part[wb][b][r][c] = s;
        }
        grid_barrier();   // includes the leading __syncthreads()
    }

    // ---- final: v from last partials (buffer (ITERS-1)&1 == 0), P_out = u*K*v ----
    {
        const int fb = (ITERS - 1) & 1;
        for (int c = tid; c < NMAT; c += TPB_SINK) {
            float s = 0.f;
            #pragma unroll
            for (int rr = 0; rr < NBLK_PER_B; rr++) s += g_part[fb][b][rr][c];
            v_s[c] = 1.0f / s;
        }
        __syncthreads();
        float vr[32];
        #pragma unroll
        for (int k = 0; k < 4; k++) {
            float4 va = *reinterpret_cast<const float4*>(&v_s[256*k + 8*lane]);
            float4 vb = *reinterpret_cast<const float4*>(&v_s[256*k + 8*lane + 4]);
            vr[8*k+0] = va.x; vr[8*k+1] = va.y; vr[8*k+2] = va.z; vr[8*k+3] = va.w;
            vr[8*k+4] = vb.x; vr[8*k+5] = vb.y; vr[8*k+6] = vb.z; vr[8*k+7] = vb.w;
        }
        for (int il = w; il < nrows; il += 16) {
            const int i = row0 + il;
            const uint4* Krow = reinterpret_cast<const uint4*>(Kb + (size_t)i * NMAT);
            float u = u_s[il];
            float* Orow = Pout + ((size_t)b << 20) + (size_t)i * NMAT;
            #pragma unroll
            for (int k = 0; k < 4; k++) {
                uint4 q = Krow[32*k + lane];
                float2 f0 = __half22float2(*reinterpret_cast<__half2*>(&q.x));
                float2 f1 = __half22float2(*reinterpret_cast<__half2*>(&q.y));
                float2 f2 = __half22float2(*reinterpret_cast<__half2*>(&q.z));
                float2 f3 = __half22float2(*reinterpret_cast<__half2*>(&q.w));
                *reinterpret_cast<float4*>(&Orow[256*k + 8*lane]) =
                    make_float4(u*f0.x*vr[8*k+0], u*f0.y*vr[8*k+1],
                                u*f1.x*vr[8*k+2], u*f1.y*vr[8*k+3]);
                *reinterpret_cast<float4*>(&Orow[256*k + 8*lane + 4]) =
                    make_float4(u*f2.x*vr[8*k+4], u*f2.y*vr[8*k+5],
                                u*f3.x*vr[8*k+6], u*f3.y*vr[8*k+7]);
            }
        }
    }
}

// ---------------- launch ----------------
extern "C" void kernel_launch(void* const* d_in, const int* in_sizes, int n_in,
                              void* d_out, int out_size) {
    const float* fA = (const float*)d_in[0];
    const float* fB = (const float*)d_in[1];
    float* out  = (float*)d_out;
    float* Pout = out;                                        // P_out: [16,1024,1024]
    float* Sout = out + (size_t)BATCH * NMAT * NMAT;          // Sij:   [16,1024,1024]

    norm_kernel<<<2048, 256>>>(fA, 0);
    norm_kernel<<<2048, 256>>>(fB, 1);

    dim3 ggrid(8, 8, BATCH);
    gemm_expk_kernel<<<ggrid, 256>>>(Sout);

    const int smem_bytes = (1024 + 128 + 16 * 1024) * sizeof(float);   // 70144
    cudaFuncSetAttribute(sinkhorn_kernel,
                         cudaFuncAttributeMaxDynamicSharedMemorySize, smem_bytes);
    sinkhorn_kernel<<<GRID_SINK, TPB_SINK, smem_bytes>>>(Pout);
}